// round 7
// baseline (speedup 1.0000x reference)
#include <cuda_runtime.h>

// ProjectionLoss fused single-kernel, occupancy-scaled:
//   thread = (b_local, view, j-quarter). Folded K@[R|t] and K@cam in REGISTERS.
//   Each thread: 16 joints (4 float4-quads), LDS.128 keypoint reads.
//   NB=4 -> 4096 blocks x 128 threads = 524k threads (2 waves), hiding
//   LDS/MUFU latency that bounded the previous 1024-block version (occ 30%).
//   Smooth-MSE in min() form (branch-free), one rcp per point-view.
//   Tail: last-arriving block reduces per-block partials in fixed order.

#define B_TOTAL 16384
#define V_NUM   8
#define J_NUM   64
#define NB      4                       // batch elements per block
#define JSPLIT  4                       // j-loop split factor
#define THREADS (NB * V_NUM * JSPLIT)   // 128
#define NBLOCKS (B_TOTAL / NB)          // 4096

#define POW_CONST 219.7120972f          // 400^0.9

__device__ float g_partials[NBLOCKS];
__device__ int   g_count = 0;

__device__ __forceinline__ float rcpa(float x) {
    float r; asm("rcp.approx.f32 %0, %1;" : "=f"(r) : "f"(x)); return r;
}
__device__ __forceinline__ float lg2a(float x) {
    float r; asm("lg2.approx.f32 %0, %1;" : "=f"(r) : "f"(x)); return r;
}
__device__ __forceinline__ float ex2a(float x) {
    float r; asm("ex2.approx.f32 %0, %1;" : "=f"(r) : "f"(x)); return r;
}
__device__ __forceinline__ float smooth_term(float d2) {
    // exact rewrite of: d2>400 ? d2^0.1 * 400^0.9 : d2  (pow branch >= d2 iff d2<=400)
    float p = ex2a(lg2a(d2) * 0.1f) * POW_CONST;
    return fminf(d2, p);
}

__global__ __launch_bounds__(THREADS, 8)
void proj_loss_fused(const float* __restrict__ gt_kps,
                     const float* __restrict__ pr_kps,
                     const float* __restrict__ gt_R,
                     const float* __restrict__ gt_t,
                     const float* __restrict__ Kmat,
                     const float* __restrict__ cam,
                     float* __restrict__ out)
{
    __shared__ __align__(16) float sGT[NB * J_NUM * 3];   // 768 floats
    __shared__ __align__(16) float sPR[NB * J_NUM * 3];   // 768
    __shared__ __align__(16) float sR [NB * V_NUM * 9];   // 288
    __shared__ __align__(16) float sT [NB * V_NUM * 3];   // 96
    __shared__ __align__(16) float sC [NB * V_NUM * 12];  // 384
    __shared__ float sK[V_NUM * 9];                       // 72
    __shared__ float sWarp[THREADS / 32];
    __shared__ int   sIsLast;

    const int tid = threadIdx.x;
    const long b0 = (long)blockIdx.x * NB;

    // ---- cooperative float4 staged loads (guarded strided loops) ----
    {
        const float4* g = (const float4*)(gt_kps + b0 * (J_NUM * 3));
        float4* s = (float4*)sGT;
        for (int i = tid; i < NB * J_NUM * 3 / 4; i += THREADS) s[i] = g[i];
    }
    {
        const float4* g = (const float4*)(pr_kps + b0 * (J_NUM * 3));
        float4* s = (float4*)sPR;
        for (int i = tid; i < NB * J_NUM * 3 / 4; i += THREADS) s[i] = g[i];
    }
    {
        const float4* g = (const float4*)(gt_R + b0 * (V_NUM * 9));
        float4* s = (float4*)sR;
        for (int i = tid; i < NB * V_NUM * 9 / 4; i += THREADS) s[i] = g[i];
    }
    {
        const float4* g = (const float4*)(gt_t + b0 * (V_NUM * 3));
        float4* s = (float4*)sT;
        for (int i = tid; i < NB * V_NUM * 3 / 4; i += THREADS) s[i] = g[i];
    }
    {
        const float4* g = (const float4*)(cam + b0 * (V_NUM * 12));
        float4* s = (float4*)sC;
        for (int i = tid; i < NB * V_NUM * 12 / 4; i += THREADS) s[i] = g[i];
    }
    if (tid < V_NUM * 9) sK[tid] = Kmat[tid];
    __syncthreads();

    // ---- per-thread: fold K into [R|t] (gt) and cam (pred), keep in regs ----
    const int bl = tid >> 5;            // 0..3  (one warp per batch element)
    const int v  = (tid >> 2) & 7;      // 0..7
    const int jh = tid & 3;             // 0..3  (j-quarter)

    float G[12];   // gt  folded 3x4: rows of K@R | K@t
    float Cm[12];  // pred folded 3x4: K@cam
    {
        const float* k  = &sK[v * 9];
        const float* R  = &sR[bl * (V_NUM * 9) + v * 9];
        const float* t  = &sT[bl * (V_NUM * 3) + v * 3];
        const float* cm = &sC[bl * (V_NUM * 12) + v * 12];
        #pragma unroll
        for (int r = 0; r < 3; r++) {
            float k0 = k[r * 3 + 0], k1 = k[r * 3 + 1], k2 = k[r * 3 + 2];
            #pragma unroll
            for (int c = 0; c < 3; c++)
                G[r * 4 + c] = fmaf(k0, R[c], fmaf(k1, R[3 + c], k2 * R[6 + c]));
            G[r * 4 + 3] = fmaf(k0, t[0], fmaf(k1, t[1], k2 * t[2]));
            #pragma unroll
            for (int c = 0; c < 4; c++)
                Cm[r * 4 + c] = fmaf(k0, cm[c], fmaf(k1, cm[4 + c], k2 * cm[8 + c]));
        }
    }

    const float4* gt4 = (const float4*)(sGT + bl * (J_NUM * 3));  // 48 float4
    const float4* pr4 = (const float4*)(sPR + bl * (J_NUM * 3));

    float acc = 0.0f;

    // ---- main loop: this thread's 16 joints = 4 quads ----
    #pragma unroll
    for (int q = 0; q < J_NUM / 4 / JSPLIT; q++) {
        const int jq = jh * (J_NUM / 4 / JSPLIT) + q;
        const float4 xa = gt4[jq * 3 + 0];
        const float4 xb = gt4[jq * 3 + 1];
        const float4 xc = gt4[jq * 3 + 2];
        const float4 pa = pr4[jq * 3 + 0];
        const float4 pb = pr4[jq * 3 + 1];
        const float4 pc = pr4[jq * 3 + 2];

        float Xs[4][3] = {{xa.x, xa.y, xa.z}, {xa.w, xb.x, xb.y},
                          {xb.z, xb.w, xc.x}, {xc.y, xc.z, xc.w}};
        float Ps[4][3] = {{pa.x, pa.y, pa.z}, {pa.w, pb.x, pb.y},
                          {pb.z, pb.w, pc.x}, {pc.y, pc.z, pc.w}};

        #pragma unroll
        for (int s = 0; s < 4; s++) {
            const float X0 = Xs[s][0], X1 = Xs[s][1], X2 = Xs[s][2];
            const float P0 = Ps[s][0], P1 = Ps[s][1], P2 = Ps[s][2];

            float u  = fmaf(G[0], X0, fmaf(G[1], X1, fmaf(G[2],  X2, G[3])));
            float vv = fmaf(G[4], X0, fmaf(G[5], X1, fmaf(G[6],  X2, G[7])));
            float w  = fmaf(G[8], X0, fmaf(G[9], X1, fmaf(G[10], X2, G[11])));

            float up = fmaf(Cm[0], P0, fmaf(Cm[1], P1, fmaf(Cm[2],  P2, Cm[3])));
            float vp = fmaf(Cm[4], P0, fmaf(Cm[5], P1, fmaf(Cm[6],  P2, Cm[7])));
            float wp = fmaf(Cm[8], P0, fmaf(Cm[9], P1, fmaf(Cm[10], P2, Cm[11])));

            // dx = u/w - up/wp = (u*wp - up*w) * rcp(w*wp): one MUFU rcp per point
            float r  = rcpa(w * wp);
            float nw = -w;
            float dx = fmaf(up, nw, u  * wp) * r;
            float dy = fmaf(vp, nw, vv * wp) * r;

            acc += smooth_term(dx * dx);
            acc += smooth_term(dy * dy);
        }
    }

    // ---- block reduction (4 warps) ----
    #pragma unroll
    for (int o = 16; o > 0; o >>= 1)
        acc += __shfl_xor_sync(0xFFFFFFFFu, acc, o);

    const int lane = tid & 31;
    const int wid  = tid >> 5;
    if (lane == 0) sWarp[wid] = acc;
    __syncthreads();

    if (wid == 0) {
        float s = (lane < THREADS / 32) ? sWarp[lane] : 0.0f;
        #pragma unroll
        for (int o = 2; o > 0; o >>= 1)
            s += __shfl_xor_sync(0xFFFFFFFFu, s, o);
        if (lane == 0) g_partials[blockIdx.x] = s;
    }

    // ---- fused finish: last-arriving block reduces partials (fixed order) ----
    __threadfence();
    if (tid == 0) {
        int c = atomicAdd(&g_count, 1);
        sIsLast = (c == NBLOCKS - 1);
    }
    __syncthreads();

    if (sIsLast) {
        float s = 0.0f;
        #pragma unroll
        for (int rep = 0; rep < NBLOCKS / THREADS; rep++)
            s += g_partials[tid + rep * THREADS];

        #pragma unroll
        for (int o = 16; o > 0; o >>= 1)
            s += __shfl_xor_sync(0xFFFFFFFFu, s, o);
        if (lane == 0) sWarp[wid] = s;
        __syncthreads();

        if (wid == 0) {
            float t = (lane < THREADS / 32) ? sWarp[lane] : 0.0f;
            #pragma unroll
            for (int o = 2; o > 0; o >>= 1)
                t += __shfl_xor_sync(0xFFFFFFFFu, t, o);
            if (lane == 0) {
                out[0] = t * (1.0f / (2.0f * (float)B_TOTAL));
                g_count = 0;   // reset for next graph replay
            }
        }
    }
}

extern "C" void kernel_launch(void* const* d_in, const int* in_sizes, int n_in,
                              void* d_out, int out_size)
{
    const float* gt_kps = (const float*)d_in[0];
    const float* pr_kps = (const float*)d_in[1];
    const float* gt_R   = (const float*)d_in[2];
    const float* gt_t   = (const float*)d_in[3];
    const float* Kmat   = (const float*)d_in[4];
    const float* cam    = (const float*)d_in[5];
    float* out = (float*)d_out;

    proj_loss_fused<<<NBLOCKS, THREADS>>>(gt_kps, pr_kps, gt_R, gt_t, Kmat, cam, out);
}

// round 8
// speedup vs baseline: 1.0425x; 1.0425x over previous
#include <cuda_runtime.h>

// ProjectionLoss fused single-kernel. Thread = (b_local, view, j-half).
// Folded K@[R|t] and K@cam in REGISTERS. 32 joints/thread (8 float4-quads).
// NB=8, JSPLIT=2 -> 2048 blocks x 128 thr: 2x warps of the NB=16 version
// (occ ~45%) at only 2x fixed overhead (vs 4x in the NB=4 version that
// regressed). Paired perspective divide: one rcp per TWO points.
// Smooth-MSE in min() form. Tail: last-arriving block reduces partials.

#define B_TOTAL 16384
#define V_NUM   8
#define J_NUM   64
#define NB      8                       // batch elements per block
#define JSPLIT  2                       // j-loop split factor
#define THREADS (NB * V_NUM * JSPLIT)   // 128
#define NBLOCKS (B_TOTAL / NB)          // 2048
#define QUADS   (J_NUM / 4 / JSPLIT)    // 8 quads (32 joints) per thread

#define POW_CONST 219.7120972f          // 400^0.9

__device__ float g_partials[NBLOCKS];
__device__ int   g_count = 0;

__device__ __forceinline__ float rcpa(float x) {
    float r; asm("rcp.approx.f32 %0, %1;" : "=f"(r) : "f"(x)); return r;
}
__device__ __forceinline__ float lg2a(float x) {
    float r; asm("lg2.approx.f32 %0, %1;" : "=f"(r) : "f"(x)); return r;
}
__device__ __forceinline__ float ex2a(float x) {
    float r; asm("ex2.approx.f32 %0, %1;" : "=f"(r) : "f"(x)); return r;
}
__device__ __forceinline__ float smooth_term(float d2) {
    // exact rewrite of: d2>400 ? d2^0.1 * 400^0.9 : d2  (pow branch >= d2 iff d2<=400)
    float p = ex2a(lg2a(d2) * 0.1f) * POW_CONST;
    return fminf(d2, p);
}

struct PV { float u, v, w, up, vp, wp; };

__device__ __forceinline__ PV project(const float* __restrict__ G,
                                      const float* __restrict__ Cm,
                                      float X0, float X1, float X2,
                                      float P0, float P1, float P2) {
    PV o;
    o.u  = fmaf(G[0], X0, fmaf(G[1], X1, fmaf(G[2],  X2, G[3])));
    o.v  = fmaf(G[4], X0, fmaf(G[5], X1, fmaf(G[6],  X2, G[7])));
    o.w  = fmaf(G[8], X0, fmaf(G[9], X1, fmaf(G[10], X2, G[11])));
    o.up = fmaf(Cm[0], P0, fmaf(Cm[1], P1, fmaf(Cm[2],  P2, Cm[3])));
    o.vp = fmaf(Cm[4], P0, fmaf(Cm[5], P1, fmaf(Cm[6],  P2, Cm[7])));
    o.wp = fmaf(Cm[8], P0, fmaf(Cm[9], P1, fmaf(Cm[10], P2, Cm[11])));
    return o;
}

__global__ __launch_bounds__(THREADS, 8)
void proj_loss_fused(const float* __restrict__ gt_kps,
                     const float* __restrict__ pr_kps,
                     const float* __restrict__ gt_R,
                     const float* __restrict__ gt_t,
                     const float* __restrict__ Kmat,
                     const float* __restrict__ cam,
                     float* __restrict__ out)
{
    __shared__ __align__(16) float sGT[NB * J_NUM * 3];
    __shared__ __align__(16) float sPR[NB * J_NUM * 3];
    __shared__ __align__(16) float sR [NB * V_NUM * 9];
    __shared__ __align__(16) float sT [NB * V_NUM * 3];
    __shared__ __align__(16) float sC [NB * V_NUM * 12];
    __shared__ float sK[V_NUM * 9];
    __shared__ float sWarp[THREADS / 32];
    __shared__ int   sIsLast;

    const int tid = threadIdx.x;
    const long b0 = (long)blockIdx.x * NB;

    // ---- cooperative float4 staged loads ----
    {
        const float4* g = (const float4*)(gt_kps + b0 * (J_NUM * 3));
        float4* s = (float4*)sGT;
        for (int i = tid; i < NB * J_NUM * 3 / 4; i += THREADS) s[i] = g[i];
    }
    {
        const float4* g = (const float4*)(pr_kps + b0 * (J_NUM * 3));
        float4* s = (float4*)sPR;
        for (int i = tid; i < NB * J_NUM * 3 / 4; i += THREADS) s[i] = g[i];
    }
    {
        const float4* g = (const float4*)(gt_R + b0 * (V_NUM * 9));
        float4* s = (float4*)sR;
        for (int i = tid; i < NB * V_NUM * 9 / 4; i += THREADS) s[i] = g[i];
    }
    {
        const float4* g = (const float4*)(gt_t + b0 * (V_NUM * 3));
        float4* s = (float4*)sT;
        for (int i = tid; i < NB * V_NUM * 3 / 4; i += THREADS) s[i] = g[i];
    }
    {
        const float4* g = (const float4*)(cam + b0 * (V_NUM * 12));
        float4* s = (float4*)sC;
        for (int i = tid; i < NB * V_NUM * 12 / 4; i += THREADS) s[i] = g[i];
    }
    if (tid < V_NUM * 9) sK[tid] = Kmat[tid];
    __syncthreads();

    // ---- per-thread fold: K@[R|t] and K@cam into registers ----
    const int bl = tid >> 4;            // 0..7
    const int v  = (tid >> 1) & 7;      // 0..7
    const int jh = tid & 1;             // 0..1 (j-half)

    float G[12];
    float Cm[12];
    {
        const float* k  = &sK[v * 9];
        const float* R  = &sR[bl * (V_NUM * 9) + v * 9];
        const float* t  = &sT[bl * (V_NUM * 3) + v * 3];
        const float* cm = &sC[bl * (V_NUM * 12) + v * 12];
        #pragma unroll
        for (int r = 0; r < 3; r++) {
            float k0 = k[r * 3 + 0], k1 = k[r * 3 + 1], k2 = k[r * 3 + 2];
            #pragma unroll
            for (int c = 0; c < 3; c++)
                G[r * 4 + c] = fmaf(k0, R[c], fmaf(k1, R[3 + c], k2 * R[6 + c]));
            G[r * 4 + 3] = fmaf(k0, t[0], fmaf(k1, t[1], k2 * t[2]));
            #pragma unroll
            for (int c = 0; c < 4; c++)
                Cm[r * 4 + c] = fmaf(k0, cm[c], fmaf(k1, cm[4 + c], k2 * cm[8 + c]));
        }
    }

    const float4* gt4 = (const float4*)(sGT + bl * (J_NUM * 3));
    const float4* pr4 = (const float4*)(sPR + bl * (J_NUM * 3));

    float acc = 0.0f;

    // ---- main loop: 8 quads of 4 joints; rcp shared across point-pairs ----
    #pragma unroll
    for (int q = 0; q < QUADS; q++) {
        const int jq = jh * QUADS + q;
        const float4 xa = gt4[jq * 3 + 0];
        const float4 xb = gt4[jq * 3 + 1];
        const float4 xc = gt4[jq * 3 + 2];
        const float4 pa = pr4[jq * 3 + 0];
        const float4 pb = pr4[jq * 3 + 1];
        const float4 pc = pr4[jq * 3 + 2];

        PV s0 = project(G, Cm, xa.x, xa.y, xa.z, pa.x, pa.y, pa.z);
        PV s1 = project(G, Cm, xa.w, xb.x, xb.y, pa.w, pb.x, pb.y);
        PV s2 = project(G, Cm, xb.z, xb.w, xc.x, pb.z, pb.w, pc.x);
        PV s3 = project(G, Cm, xc.y, xc.z, xc.w, pc.y, pc.z, pc.w);

        // Pair 0-1 and 2-3: one rcp per pair of points.
        // zK = wK*wpK; dK = (uK*wpK - upK*wK) / zK
        {
            float z0 = s0.w * s0.wp;
            float z1 = s1.w * s1.wp;
            float rr = rcpa(z0 * z1);
            float r0 = rr * z1;
            float r1 = rr * z0;
            float dx0 = fmaf(s0.up, -s0.w, s0.u * s0.wp) * r0;
            float dy0 = fmaf(s0.vp, -s0.w, s0.v * s0.wp) * r0;
            float dx1 = fmaf(s1.up, -s1.w, s1.u * s1.wp) * r1;
            float dy1 = fmaf(s1.vp, -s1.w, s1.v * s1.wp) * r1;
            acc += smooth_term(dx0 * dx0);
            acc += smooth_term(dy0 * dy0);
            acc += smooth_term(dx1 * dx1);
            acc += smooth_term(dy1 * dy1);
        }
        {
            float z2 = s2.w * s2.wp;
            float z3 = s3.w * s3.wp;
            float rr = rcpa(z2 * z3);
            float r2 = rr * z3;
            float r3 = rr * z2;
            float dx2 = fmaf(s2.up, -s2.w, s2.u * s2.wp) * r2;
            float dy2 = fmaf(s2.vp, -s2.w, s2.v * s2.wp) * r2;
            float dx3 = fmaf(s3.up, -s3.w, s3.u * s3.wp) * r3;
            float dy3 = fmaf(s3.vp, -s3.w, s3.v * s3.wp) * r3;
            acc += smooth_term(dx2 * dx2);
            acc += smooth_term(dy2 * dy2);
            acc += smooth_term(dx3 * dx3);
            acc += smooth_term(dy3 * dy3);
        }
    }

    // ---- block reduction (4 warps) ----
    #pragma unroll
    for (int o = 16; o > 0; o >>= 1)
        acc += __shfl_xor_sync(0xFFFFFFFFu, acc, o);

    const int lane = tid & 31;
    const int wid  = tid >> 5;
    if (lane == 0) sWarp[wid] = acc;
    __syncthreads();

    if (wid == 0) {
        float s = (lane < THREADS / 32) ? sWarp[lane] : 0.0f;
        #pragma unroll
        for (int o = 2; o > 0; o >>= 1)
            s += __shfl_xor_sync(0xFFFFFFFFu, s, o);
        if (lane == 0) g_partials[blockIdx.x] = s;
    }

    // ---- fused finish: last-arriving block reduces partials ----
    __threadfence();
    if (tid == 0) {
        int c = atomicAdd(&g_count, 1);
        sIsLast = (c == NBLOCKS - 1);
    }
    __syncthreads();

    if (sIsLast) {
        float s = 0.0f;
        #pragma unroll
        for (int rep = 0; rep < NBLOCKS / THREADS; rep++)
            s += g_partials[tid + rep * THREADS];

        #pragma unroll
        for (int o = 16; o > 0; o >>= 1)
            s += __shfl_xor_sync(0xFFFFFFFFu, s, o);
        if (lane == 0) sWarp[wid] = s;
        __syncthreads();

        if (wid == 0) {
            float t = (lane < THREADS / 32) ? sWarp[lane] : 0.0f;
            #pragma unroll
            for (int o = 2; o > 0; o >>= 1)
                t += __shfl_xor_sync(0xFFFFFFFFu, t, o);
            if (lane == 0) {
                out[0] = t * (1.0f / (2.0f * (float)B_TOTAL));
                g_count = 0;   // reset for next graph replay
            }
        }
    }
}

extern "C" void kernel_launch(void* const* d_in, const int* in_sizes, int n_in,
                              void* d_out, int out_size)
{
    const float* gt_kps = (const float*)d_in[0];
    const float* pr_kps = (const float*)d_in[1];
    const float* gt_R   = (const float*)d_in[2];
    const float* gt_t   = (const float*)d_in[3];
    const float* Kmat   = (const float*)d_in[4];
    const float* cam    = (const float*)d_in[5];
    float* out = (float*)d_out;

    proj_loss_fused<<<NBLOCKS, THREADS>>>(gt_kps, pr_kps, gt_R, gt_t, Kmat, cam, out);
}